// round 1
// baseline (speedup 1.0000x reference)
#include <cuda_runtime.h>
#include <cstdint>

#define NMAX 100000

// Scratch (device globals: no allocation allowed in kernel_launch)
__device__ float  g_deg[NMAX];
__device__ float  g_dinv[NMAX];
__device__ float  g_p[NMAX];
__device__ float  g_t[NMAX];
__device__ float2 g_r[NMAX];
__device__ float2 g_acc[NMAX];

// ---------------- node kernels ----------------

__global__ void k_init(int n) {
    int i = blockIdx.x * blockDim.x + threadIdx.x;
    if (i < n) g_deg[i] = 1.0f;  // self-loop contributes 1 to degree
}

__global__ void k_node1(const float* __restrict__ x, int n) {
    int i = blockIdx.x * blockDim.x + threadIdx.x;
    if (i < n) {
        float d = rsqrtf(g_deg[i]);
        g_dinv[i] = d;
        float p = d * x[i];
        g_p[i] = p;
        g_t[i] = p;  // self-loop term: s1 = dinv*(sum_e p[src] + p[v])
    }
}

__global__ void k_node2(const float* __restrict__ W1, const float* __restrict__ b1,
                        const float* __restrict__ W2, int n) {
    int i = blockIdx.x * blockDim.x + threadIdx.x;
    if (i < n) {
        float dv = g_dinv[i];
        float s = dv * g_t[i];  // layer-1 aggregated scalar
        float g0 = 0.0f, g1 = 0.0f;
        #pragma unroll
        for (int j = 0; j < 16; j++) {
            float h = fmaxf(fmaf(s, __ldg(&W1[j]), __ldg(&b1[j])), 0.0f);
            g0 = fmaf(h, __ldg(&W2[2 * j + 0]), g0);
            g1 = fmaf(h, __ldg(&W2[2 * j + 1]), g1);
        }
        float2 r = make_float2(dv * g0, dv * g1);
        g_r[i] = r;
        g_acc[i] = r;  // self-loop term folded into the accumulator init
    }
}

__global__ void k_out(const float* __restrict__ b2, float* __restrict__ out, int n) {
    int i = blockIdx.x * blockDim.x + threadIdx.x;
    if (i < n) {
        float dv = g_dinv[i];
        float2 a = g_acc[i];
        float z0 = fmaf(dv, a.x, __ldg(&b2[0]));
        float z1 = fmaf(dv, a.y, __ldg(&b2[1]));
        float m = fmaxf(z0, z1);
        float lse = m + logf(expf(z0 - m) + expf(z1 - m));
        out[2 * i + 0] = z0 - lse;
        out[2 * i + 1] = z1 - lse;
    }
}

// ---------------- edge kernels (4 edges/thread, int4 loads) ----------------

__global__ void k_deg(const int* __restrict__ dst, int E) {
    int i = blockIdx.x * blockDim.x + threadIdx.x;
    int base = i * 4;
    if (base + 3 < E) {
        int4 d = *reinterpret_cast<const int4*>(dst + base);
        atomicAdd(&g_deg[d.x], 1.0f);
        atomicAdd(&g_deg[d.y], 1.0f);
        atomicAdd(&g_deg[d.z], 1.0f);
        atomicAdd(&g_deg[d.w], 1.0f);
    } else {
        for (int e = base; e < E; ++e) atomicAdd(&g_deg[dst[e]], 1.0f);
    }
}

__global__ void k_agg1(const int* __restrict__ src, const int* __restrict__ dst, int E) {
    int i = blockIdx.x * blockDim.x + threadIdx.x;
    int base = i * 4;
    if (base + 3 < E) {
        int4 s = *reinterpret_cast<const int4*>(src + base);
        int4 d = *reinterpret_cast<const int4*>(dst + base);
        atomicAdd(&g_t[d.x], __ldg(&g_p[s.x]));
        atomicAdd(&g_t[d.y], __ldg(&g_p[s.y]));
        atomicAdd(&g_t[d.z], __ldg(&g_p[s.z]));
        atomicAdd(&g_t[d.w], __ldg(&g_p[s.w]));
    } else {
        for (int e = base; e < E; ++e) atomicAdd(&g_t[dst[e]], __ldg(&g_p[src[e]]));
    }
}

__device__ __forceinline__ void red_add_v2(float2* addr, float2 v) {
    asm volatile("red.global.add.v2.f32 [%0], {%1, %2};"
                 :: "l"(addr), "f"(v.x), "f"(v.y) : "memory");
}

__global__ void k_agg2(const int* __restrict__ src, const int* __restrict__ dst, int E) {
    int i = blockIdx.x * blockDim.x + threadIdx.x;
    int base = i * 4;
    if (base + 3 < E) {
        int4 s = *reinterpret_cast<const int4*>(src + base);
        int4 d = *reinterpret_cast<const int4*>(dst + base);
        red_add_v2(&g_acc[d.x], __ldg(&g_r[s.x]));
        red_add_v2(&g_acc[d.y], __ldg(&g_r[s.y]));
        red_add_v2(&g_acc[d.z], __ldg(&g_r[s.z]));
        red_add_v2(&g_acc[d.w], __ldg(&g_r[s.w]));
    } else {
        for (int e = base; e < E; ++e) red_add_v2(&g_acc[dst[e]], __ldg(&g_r[src[e]]));
    }
}

// ---------------- launch ----------------

extern "C" void kernel_launch(void* const* d_in, const int* in_sizes, int n_in,
                              void* d_out, int out_size) {
    const float* x  = (const float*)d_in[0];
    const int*   ei = (const int*)  d_in[1];
    const float* W1 = (const float*)d_in[2];
    const float* b1 = (const float*)d_in[3];
    const float* W2 = (const float*)d_in[4];
    const float* b2 = (const float*)d_in[5];
    int n = in_sizes[0];        // x is [N, 1]
    int E = in_sizes[1] / 2;    // edge_index is [2, E]
    const int* src = ei;
    const int* dst = ei + E;

    const int TB = 256;
    int nb_n = (n + TB - 1) / TB;
    int e4   = (E + 3) / 4;
    int nb_e = (e4 + TB - 1) / TB;

    k_init <<<nb_n, TB>>>(n);
    k_deg  <<<nb_e, TB>>>(dst, E);
    k_node1<<<nb_n, TB>>>(x, n);
    k_agg1 <<<nb_e, TB>>>(src, dst, E);
    k_node2<<<nb_n, TB>>>(W1, b1, W2, n);
    k_agg2 <<<nb_e, TB>>>(src, dst, E);
    k_out  <<<nb_n, TB>>>(b2, (float*)d_out, n);
}

// round 2
// speedup vs baseline: 1.2773x; 1.2773x over previous
#include <cuda_runtime.h>
#include <cuda_fp16.h>
#include <cstdint>

#define NMAX 100000
#define NHALF 50000            // node range per agg pass
#define HWORDS ((NMAX + 1) / 2)  // packed uint16x2 histogram words

// Scratch (device globals: no allocation allowed)
__device__ uint32_t g_degpack[HWORDS];
__device__ float    g_dinv[NMAX];
__device__ float    g_p[NMAX];
__device__ float    g_t[NMAX];
__device__ __half2  g_rh[NMAX];
__device__ float2   g_acc[NMAX];

// ---------------- node kernels ----------------

__global__ void k_init() {
    int i = blockIdx.x * blockDim.x + threadIdx.x;
    if (i < HWORDS) g_degpack[i] = 0u;
}

__global__ void k_node1(const float* __restrict__ x, int n) {
    int i = blockIdx.x * blockDim.x + threadIdx.x;
    if (i < n) {
        uint32_t pack = g_degpack[i >> 1];
        uint32_t cnt = (pack >> ((i & 1) * 16)) & 0xFFFFu;
        float d = rsqrtf(1.0f + (float)cnt);   // +1 = self-loop
        g_dinv[i] = d;
        float p = d * x[i];
        g_p[i] = p;
        g_t[i] = p;  // self-loop term of layer-1 aggregation
    }
}

__global__ void k_node2(const float* __restrict__ W1, const float* __restrict__ b1,
                        const float* __restrict__ W2, int n) {
    int i = blockIdx.x * blockDim.x + threadIdx.x;
    if (i < n) {
        float dv = g_dinv[i];
        float s = dv * g_t[i];  // layer-1 aggregated scalar
        float g0 = 0.0f, g1 = 0.0f;
        #pragma unroll
        for (int j = 0; j < 16; j++) {
            float h = fmaxf(fmaf(s, __ldg(&W1[j]), __ldg(&b1[j])), 0.0f);
            g0 = fmaf(h, __ldg(&W2[2 * j + 0]), g0);
            g1 = fmaf(h, __ldg(&W2[2 * j + 1]), g1);
        }
        float2 r = make_float2(dv * g0, dv * g1);
        g_rh[i] = __float22half2_rn(r);  // half precision for L1-resident gathers
        g_acc[i] = r;                    // self-loop term stays fp32
    }
}

__global__ void k_out(const float* __restrict__ b2, float* __restrict__ out, int n) {
    int i = blockIdx.x * blockDim.x + threadIdx.x;
    if (i < n) {
        float dv = g_dinv[i];
        float2 a = g_acc[i];
        float z0 = fmaf(dv, a.x, __ldg(&b2[0]));
        float z1 = fmaf(dv, a.y, __ldg(&b2[1]));
        float m = fmaxf(z0, z1);
        float lse = m + logf(expf(z0 - m) + expf(z1 - m));
        out[2 * i + 0] = z0 - lse;
        out[2 * i + 1] = z1 - lse;
    }
}

// ---------------- degree: smem-privatized packed histogram ----------------

__global__ void k_deg(const int* __restrict__ dst, int E) {
    extern __shared__ uint32_t hist[];  // HWORDS words = 200KB
    for (int i = threadIdx.x; i < HWORDS; i += blockDim.x) hist[i] = 0u;
    __syncthreads();

    int e4 = E >> 2;
    int stride = gridDim.x * blockDim.x;
    for (int i = blockIdx.x * blockDim.x + threadIdx.x; i < e4; i += stride) {
        int4 d = __ldcs(reinterpret_cast<const int4*>(dst) + i);
        atomicAdd(&hist[d.x >> 1], 1u << ((d.x & 1) * 16));
        atomicAdd(&hist[d.y >> 1], 1u << ((d.y & 1) * 16));
        atomicAdd(&hist[d.z >> 1], 1u << ((d.z & 1) * 16));
        atomicAdd(&hist[d.w >> 1], 1u << ((d.w & 1) * 16));
    }
    // tail (E not multiple of 4)
    if (blockIdx.x == 0) {
        for (int e = (e4 << 2) + (int)threadIdx.x; e < E; e += blockDim.x) {
            int d = dst[e];
            atomicAdd(&hist[d >> 1], 1u << ((d & 1) * 16));
        }
    }
    __syncthreads();

    for (int i = threadIdx.x; i < HWORDS; i += blockDim.x) {
        uint32_t v = hist[i];
        if (v) atomicAdd(&g_degpack[i], v);
    }
}

// ---------------- edge aggregation (src-range filtered for L1 residency) ----

__global__ void k_agg1(const int* __restrict__ src, const int* __restrict__ dst,
                       int E, int lo, int hi) {
    int i = blockIdx.x * blockDim.x + threadIdx.x;
    int base = i * 4;
    if (base + 3 < E) {
        int4 s = __ldcs(reinterpret_cast<const int4*>(src) + i);
        int4 d = __ldcs(reinterpret_cast<const int4*>(dst) + i);
        if (s.x >= lo && s.x < hi) atomicAdd(&g_t[d.x], __ldg(&g_p[s.x]));
        if (s.y >= lo && s.y < hi) atomicAdd(&g_t[d.y], __ldg(&g_p[s.y]));
        if (s.z >= lo && s.z < hi) atomicAdd(&g_t[d.z], __ldg(&g_p[s.z]));
        if (s.w >= lo && s.w < hi) atomicAdd(&g_t[d.w], __ldg(&g_p[s.w]));
    } else if (base < E) {
        for (int e = base; e < E; ++e) {
            int sv = src[e];
            if (sv >= lo && sv < hi) atomicAdd(&g_t[dst[e]], __ldg(&g_p[sv]));
        }
    }
}

__device__ __forceinline__ void red_add_v2(float2* addr, float x, float y) {
    asm volatile("red.global.add.v2.f32 [%0], {%1, %2};"
                 :: "l"(addr), "f"(x), "f"(y) : "memory");
}

__global__ void k_agg2(const int* __restrict__ src, const int* __restrict__ dst,
                       int E, int lo, int hi) {
    int i = blockIdx.x * blockDim.x + threadIdx.x;
    int base = i * 4;
    if (base + 3 < E) {
        int4 s = __ldcs(reinterpret_cast<const int4*>(src) + i);
        int4 d = __ldcs(reinterpret_cast<const int4*>(dst) + i);
        if (s.x >= lo && s.x < hi) {
            float2 r = __half22float2(__ldg(&g_rh[s.x]));
            red_add_v2(&g_acc[d.x], r.x, r.y);
        }
        if (s.y >= lo && s.y < hi) {
            float2 r = __half22float2(__ldg(&g_rh[s.y]));
            red_add_v2(&g_acc[d.y], r.x, r.y);
        }
        if (s.z >= lo && s.z < hi) {
            float2 r = __half22float2(__ldg(&g_rh[s.z]));
            red_add_v2(&g_acc[d.z], r.x, r.y);
        }
        if (s.w >= lo && s.w < hi) {
            float2 r = __half22float2(__ldg(&g_rh[s.w]));
            red_add_v2(&g_acc[d.w], r.x, r.y);
        }
    } else if (base < E) {
        for (int e = base; e < E; ++e) {
            int sv = src[e];
            if (sv >= lo && sv < hi) {
                float2 r = __half22float2(__ldg(&g_rh[sv]));
                red_add_v2(&g_acc[dst[e]], r.x, r.y);
            }
        }
    }
}

// ---------------- launch ----------------

extern "C" void kernel_launch(void* const* d_in, const int* in_sizes, int n_in,
                              void* d_out, int out_size) {
    const float* x  = (const float*)d_in[0];
    const int*   ei = (const int*)  d_in[1];
    const float* W1 = (const float*)d_in[2];
    const float* b1 = (const float*)d_in[3];
    const float* W2 = (const float*)d_in[4];
    const float* b2 = (const float*)d_in[5];
    int n = in_sizes[0];        // x is [N, 1]
    int E = in_sizes[1] / 2;    // edge_index is [2, E]
    const int* src = ei;
    const int* dst = ei + E;

    const int HIST_BYTES = HWORDS * 4;  // 200 KB
    cudaFuncSetAttribute(k_deg, cudaFuncAttributeMaxDynamicSharedMemorySize, HIST_BYTES);

    const int TB = 256;
    int nb_n = (n + TB - 1) / TB;
    int nb_h = (HWORDS + TB - 1) / TB;
    int e4   = (E + 3) / 4;
    int nb_e = (e4 + TB - 1) / TB;

    k_init <<<nb_h, TB>>>();
    k_deg  <<<148, 1024, HIST_BYTES>>>(dst, E);
    k_node1<<<nb_n, TB>>>(x, n);
    k_agg1 <<<nb_e, TB>>>(src, dst, E, 0, NHALF);
    k_agg1 <<<nb_e, TB>>>(src, dst, E, NHALF, NMAX);
    k_node2<<<nb_n, TB>>>(W1, b1, W2, n);
    k_agg2 <<<nb_e, TB>>>(src, dst, E, 0, NHALF);
    k_agg2 <<<nb_e, TB>>>(src, dst, E, NHALF, NMAX);
    k_out  <<<nb_n, TB>>>(b2, (float*)d_out, n);
}